// round 3
// baseline (speedup 1.0000x reference)
#include <cuda_runtime.h>
#include <math.h>

#define DIMC 96
#define NVOX (DIMC*DIMC*DIMC)          // 884736
#define NL   10
#define RAD  9
#define KSZ  19
#define MU2_OVER_L 0.001f               // 0.1^2 / 10

// ---------------- scratch (no allocations allowed) ----------------
__device__ float d_img [NVOX];
__device__ float d_bufA[3*NVOX];
__device__ float d_bufB[3*NVOX];
__device__ float d_rdA [NVOX];
__device__ float d_rdB [NVOX];
__device__ float d_phiA[3*NVOX];
__device__ float d_phiB[3*NVOX];
__device__ float d_gk  [KSZ];

// linspace(-1,1,96)[p] exactly as computed in fp32: fl(p*fl(2/95)) + (-1)
__device__ __forceinline__ float nlin(int p) {
    return __fadd_rn(__fmul_rn((float)p, 2.0f/95.0f), -1.0f);
}
// Reference-exact pixel coordinate: ((fl(n - fl(v/10)) + 1)*0.5)*95
// The fl(n - v/10) flush at the 0-face (n=-1) is load-bearing: it decides
// which side of the trilerp discontinuity at coordinate 0 we sample.
__device__ __forceinline__ float defm_pix(float n, float v) {
    float t = __fadd_rn(n, -__fdiv_rn(v, 10.0f));
    t = __fadd_rn(t, 1.0f);
    t = __fmul_rn(t, 0.5f);
    return __fmul_rn(t, 95.0f);
}
// Reference-exact pixel coordinate from a normalized grid value (phi path)
__device__ __forceinline__ float grid_pix(float g) {
    float t = __fadd_rn(g, 1.0f);
    t = __fmul_rn(t, 0.5f);
    return __fmul_rn(t, 95.0f);
}

// Reference-exact trilinear sample with the reference's border behavior.
// X indexes stride-1 axis, Y stride-96, Z stride-9216.
__device__ __forceinline__ float trilerp(const float* __restrict__ p,
                                         float X, float Y, float Z) {
    float xf = floorf(X), yf = floorf(Y), zf = floorf(Z);
    float fx = X - xf, fy = Y - yf, fz = Z - zf;
    int x0 = min(max((int)xf, 0), DIMC-1); int x1 = min(x0 + 1, DIMC-1);
    int y0 = min(max((int)yf, 0), DIMC-1); int y1 = min(y0 + 1, DIMC-1);
    int z0 = min(max((int)zf, 0), DIMC-1); int z1 = min(z0 + 1, DIMC-1);
    int b00 = (z0*DIMC + y0)*DIMC, b01 = (z0*DIMC + y1)*DIMC;
    int b10 = (z1*DIMC + y0)*DIMC, b11 = (z1*DIMC + y1)*DIMC;
    float c000 = p[b00+x0], c001 = p[b00+x1];
    float c010 = p[b01+x0], c011 = p[b01+x1];
    float c100 = p[b10+x0], c101 = p[b10+x1];
    float c110 = p[b11+x0], c111 = p[b11+x1];
    float lo = (c000*(1.f-fx)+c001*fx)*(1.f-fy) + (c010*(1.f-fx)+c011*fx)*fy;
    float hi = (c100*(1.f-fx)+c101*fx)*(1.f-fy) + (c110*(1.f-fx)+c111*fx)*fy;
    return lo*(1.f-fz) + hi*fz;
}

// ---------------- init: gk, img=source, res[0]=z0, rd=0, phi=idgrid ----------
__global__ void k_init(const float* __restrict__ src,
                       const float* __restrict__ z0,
                       float* __restrict__ outRes0) {
    int i = blockIdx.x*blockDim.x + threadIdx.x;
    if (i < KSZ) {
        float dd = (float)(i - RAD) / 3.0f;
        float w = expf(-0.5f * dd * dd);
        float s = 0.f;
        #pragma unroll
        for (int t = 0; t < KSZ; t++) {
            float e = (float)(t - RAD) / 3.0f;
            s += expf(-0.5f * e * e);
        }
        d_gk[i] = w / s;
    }
    if (i >= NVOX) return;
    d_img[i] = src[i];
    outRes0[i] = z0[i];
    d_rdA[i] = 0.f;
    int x = i % DIMC, y = (i/DIMC) % DIMC, z = i/(DIMC*DIMC);
    d_phiA[i]          = nlin(x);
    d_phiA[NVOX+i]     = nlin(y);
    d_phiA[2*NVOX+i]   = nlin(z);
}

// ---- pass 1: gradient (replicate pad) + u=-res*g + W-axis blur, write grads -
__global__ void k_blurW_grad(const float* __restrict__ resOld,
                             float* __restrict__ gradsOut) {
    __shared__ float sh[8][DIMC];
    __shared__ float s_gk[KSZ];
    int tx = threadIdx.x, ty = threadIdx.y;
    int tid = ty*32 + tx;
    int c = blockIdx.y;
    int row = blockIdx.x*8 + ty;          // 0..9215
    int z = row / DIMC, y = row % DIMC;
    int ibase = (z*DIMC + y)*DIMC;
    if (tid < KSZ) s_gk[tid] = d_gk[tid];

    #pragma unroll
    for (int k = 0; k < 3; k++) {
        int x = tx + 32*k;
        int i = ibase + x;
        float g;
        if (c == 0) {
            g = 0.5f*(d_img[i + (x < DIMC-1 ? 1 : 0)] - d_img[i - (x > 0 ? 1 : 0)]);
        } else if (c == 1) {
            g = 0.5f*(d_img[i + (y < DIMC-1 ? DIMC : 0)] - d_img[i - (y > 0 ? DIMC : 0)]);
        } else {
            g = 0.5f*(d_img[i + (z < DIMC-1 ? DIMC*DIMC : 0)] - d_img[i - (z > 0 ? DIMC*DIMC : 0)]);
        }
        gradsOut[(size_t)c*NVOX + i] = g;
        sh[ty][x] = -resOld[i] * g;
    }
    __syncthreads();
    #pragma unroll
    for (int k = 0; k < 3; k++) {
        int x = tx + 32*k;
        float s = 0.f;
        #pragma unroll
        for (int t = 0; t < KSZ; t++) {
            int q = x + t - RAD;
            if ((unsigned)q < (unsigned)DIMC) s += s_gk[t] * sh[ty][q];
        }
        d_bufA[(size_t)c*NVOX + ibase + x] = s;
    }
}

// ---- pass 2: H-axis blur bufA->bufB. grid (3 xchunk, 96 z, 3 c), block (32,8)
__global__ void k_blurH() {
    __shared__ float sh[DIMC][32];
    __shared__ float s_gk[KSZ];
    int tx = threadIdx.x, ty = threadIdx.y;
    int tid = ty*32 + tx;
    int x0 = blockIdx.x*32, z = blockIdx.y, c = blockIdx.z;
    const float* __restrict__ in = d_bufA + (size_t)c*NVOX;
    float* __restrict__ out      = d_bufB + (size_t)c*NVOX;
    if (tid < KSZ) s_gk[tid] = d_gk[tid];
    #pragma unroll
    for (int k = 0; k < 12; k++) {
        int y = ty + 8*k;
        sh[y][tx] = in[(z*DIMC + y)*DIMC + x0 + tx];
    }
    __syncthreads();
    #pragma unroll
    for (int k = 0; k < 12; k++) {
        int y = ty + 8*k;
        float s = 0.f;
        #pragma unroll
        for (int t = 0; t < KSZ; t++) {
            int q = y + t - RAD;
            if ((unsigned)q < (unsigned)DIMC) s += s_gk[t] * sh[q][tx];
        }
        out[(z*DIMC + y)*DIMC + x0 + tx] = s;
    }
}

// ---- pass 3: D-axis blur bufB->bufA (= v) + transposed fields write ---------
__global__ void k_blurD_fields(float* __restrict__ fieldsOut) {
    __shared__ float sh[DIMC][32];
    __shared__ float sh2[DIMC][33];
    __shared__ float s_gk[KSZ];
    int tx = threadIdx.x, ty = threadIdx.y;
    int tid = ty*32 + tx;
    int x0 = blockIdx.x*32, h = blockIdx.y, c = blockIdx.z;
    const float* __restrict__ in = d_bufB + (size_t)c*NVOX;
    float* __restrict__ out      = d_bufA + (size_t)c*NVOX;
    if (tid < KSZ) s_gk[tid] = d_gk[tid];
    #pragma unroll
    for (int k = 0; k < 12; k++) {
        int z = ty + 8*k;
        sh[z][tx] = in[(z*DIMC + h)*DIMC + x0 + tx];
    }
    __syncthreads();
    #pragma unroll
    for (int k = 0; k < 12; k++) {
        int z = ty + 8*k;
        float s = 0.f;
        #pragma unroll
        for (int t = 0; t < KSZ; t++) {
            int q = z + t - RAD;
            if ((unsigned)q < (unsigned)DIMC) s += s_gk[t] * sh[q][tx];
        }
        out[(z*DIMC + h)*DIMC + x0 + tx] = s;
        sh2[z][tx] = s;
    }
    __syncthreads();
    // fields[3*((w*96+h)*96+d)+c] = v_c[(d*96+h)*96+w] ; coalesced in d=tx
    #pragma unroll
    for (int dk = 0; dk < 3; dk++) {
        int d = tx + 32*dk;
        #pragma unroll
        for (int wk = 0; wk < 4; wk++) {
            int w = ty + 8*wk;
            fieldsOut[3*((((size_t)(x0 + w))*DIMC + h)*DIMC + d) + c] = sh2[d][w];
        }
    }
}

// ---- f = div(res*v); res_new = res - f/32/L. Shared halo tile. --------------
__global__ void k_div(const float* __restrict__ resOld,
                      float* __restrict__ resNew) {
    __shared__ float rs [3*10*34];
    __shared__ float v0s[3*10*34];
    __shared__ float v1s[3*10*34];
    __shared__ float v2s[3*10*34];
    int tx = threadIdx.x, ty = threadIdx.y;
    int tid = ty*32 + tx;
    int x0 = blockIdx.x*32, y0 = blockIdx.y*8, z = blockIdx.z;

    for (int li = tid; li < 3*10*34; li += 256) {
        int zp = li / 340, r2 = li % 340;
        int yy = r2 / 34, xx = r2 % 34;
        int gz = z + zp - 1, gy = y0 + yy - 1, gx = x0 + xx - 1;
        bool inb = (unsigned)gz < DIMC && (unsigned)gy < DIMC && (unsigned)gx < DIMC;
        int gi = (gz*DIMC + gy)*DIMC + gx;
        rs [li] = inb ? resOld[gi]          : 0.f;
        v0s[li] = inb ? d_bufA[gi]          : 0.f;
        v1s[li] = inb ? d_bufA[NVOX + gi]   : 0.f;
        v2s[li] = inb ? d_bufA[2*NVOX + gi] : 0.f;
    }
    __syncthreads();

    const float sw[3]  = {1.f, 2.f, 1.f};
    const float dwt[3] = {-1.f, 0.f, 1.f};
    float acc = 0.f;
    #pragma unroll
    for (int a = 0; a < 3; a++) {
        #pragma unroll
        for (int b = 0; b < 3; b++) {
            #pragma unroll
            for (int cc = 0; cc < 3; cc++) {
                int si = (a*10 + (ty + b))*34 + (tx + cc);
                float wx = sw[a]*sw[b]*dwt[cc];
                float wy = sw[a]*dwt[b]*sw[cc];
                float wz = dwt[a]*sw[b]*sw[cc];
                float r = rs[si];
                acc += (r*v0s[si])*wx + (r*v1s[si])*wy + (r*v2s[si])*wz;
            }
        }
    }
    int ci = (1*10 + (ty+1))*34 + (tx+1);
    float f = __fdiv_rn(acc * (1.0f/32.0f), 10.0f);
    resNew[(z*DIMC + y0 + ty)*DIMC + x0 + tx] = rs[ci] - f;
}

// ---- fused: rd warp + phi warp + image update (+ final outputs) -------------
__global__ void k_warp(int par,
                       const float* __restrict__ resNew,
                       const float* __restrict__ fields,
                       const float* __restrict__ src,
                       const float* __restrict__ seg,
                       float* __restrict__ outImg,
                       float* __restrict__ outRd) {
    int i = blockIdx.x*blockDim.x + threadIdx.x;
    if (i >= NVOX) return;
    const float* __restrict__ rdIn  = par ? d_rdB  : d_rdA;
    float* __restrict__       rdOut = par ? d_rdA  : d_rdB;
    const float* __restrict__ phiIn  = par ? d_phiB : d_phiA;
    float* __restrict__       phiOut = par ? d_phiA : d_phiB;
    int x = i % DIMC, y = (i/DIMC) % DIMC, z = i/(DIMC*DIMC);
    float nx = nlin(x), ny = nlin(y), nz = nlin(z);

    // rd: coords use v at transposed index = fields[3i+c]; literal defm chain
    float Xr = defm_pix(nx, fields[3*(size_t)i+0]);
    float Yr = defm_pix(ny, fields[3*(size_t)i+1]);
    float Zr = defm_pix(nz, fields[3*(size_t)i+2]);
    float rdv = trilerp(rdIn, Xr, Yr, Zr) + resNew[i];
    rdOut[i] = rdv;

    // phi: X<-v2, Y<-v1, Z<-v0 at index i (from the double transpose)
    float Xp = defm_pix(nx, d_bufA[2*NVOX+i]);
    float Yp = defm_pix(ny, d_bufA[NVOX+i]);
    float Zp = defm_pix(nz, d_bufA[i]);
    float p0 = trilerp(phiIn,          Xp, Yp, Zp);
    float p1 = trilerp(phiIn + NVOX,   Xp, Yp, Zp);
    float p2 = trilerp(phiIn + 2*NVOX, Xp, Yp, Zp);
    phiOut[i]        = p0;
    phiOut[NVOX+i]   = p1;
    phiOut[2*NVOX+i] = p2;

    // image = warp(src, phi) + rd * (mu^2/L) * warp(seg, phi); literal chain
    float Xi = grid_pix(p0);
    float Yi = grid_pix(p1);
    float Zi = grid_pix(p2);
    float sv = trilerp(src, Xi, Yi, Zi);
    float mk = trilerp(seg, Xi, Yi, Zi);
    float val = sv + rdv * MU2_OVER_L * mk;
    d_img[i] = val;
    if (outImg) { outImg[i] = val; outRd[i] = rdv; }
}

extern "C" void kernel_launch(void* const* d_in, const int* in_sizes, int n_in,
                              void* d_out, int out_size) {
    (void)in_sizes; (void)n_in; (void)out_size;
    const float* src = (const float*)d_in[0];
    // d_in[1] = target (unused by reference computation)
    const float* seg = (const float*)d_in[2];
    const float* z0  = (const float*)d_in[3];

    float* out       = (float*)d_out;
    float* outImage  = out;                                   // [1,1,96,96,96]
    float* outFields = outImage + NVOX;                       // [10,1,96,96,96,3]
    float* outGrads  = outFields + (size_t)NL*3*NVOX;         // [10,1,1,3,96,96,96]
    float* outRes    = outGrads  + (size_t)NL*3*NVOX;         // [11,1,1,96,96,96]
    float* outRd     = outRes    + (size_t)(NL+1)*NVOX;       // [1,1,96,96,96]

    const int TB = 256;
    const int gN = (NVOX + TB - 1) / TB;

    k_init<<<gN, TB>>>(src, z0, outRes);

    dim3 blk(32, 8);
    dim3 gW(DIMC*DIMC/8, 3);
    dim3 gH(3, DIMC, 3);
    dim3 gD(3, DIMC, 3);
    dim3 gV(3, DIMC/8, DIMC);

    for (int it = 0; it < NL; it++) {
        int par = it & 1;
        const float* resOld = outRes + (size_t)it     * NVOX;
        float*       resNew = outRes + (size_t)(it+1) * NVOX;
        float*       fields = outFields + (size_t)it * 3 * NVOX;
        bool last = (it == NL-1);

        k_blurW_grad<<<gW, blk>>>(resOld, outGrads + (size_t)it*3*NVOX);
        k_blurH<<<gH, blk>>>();
        k_blurD_fields<<<gD, blk>>>(fields);
        k_div<<<gV, blk>>>(resOld, resNew);
        k_warp<<<gN, TB>>>(par, resNew, fields, src, seg,
                           last ? outImage : (float*)nullptr,
                           last ? outRd    : (float*)nullptr);
    }
}

// round 4
// speedup vs baseline: 1.2912x; 1.2912x over previous
#include <cuda_runtime.h>
#include <math.h>

#define DIMC 96
#define NVOX (DIMC*DIMC*DIMC)          // 884736
#define NL   10
#define RAD  9
#define KSZ  19
#define MU2_OVER_L 0.001f               // 0.1^2 / 10

// ---------------- scratch (no allocations allowed) ----------------
__device__ float  d_img [NVOX];
__device__ float  d_bufA[3*NVOX];       // v (after D blur)
__device__ float  d_bufB[3*NVOX];       // after W+H blur
__device__ float  d_rdA [NVOX];
__device__ float  d_rdB [NVOX];
__device__ float4 d_phi4A[NVOX];
__device__ float4 d_phi4B[NVOX];
__device__ float2 d_ss  [NVOX];         // (source, seg) packed
__device__ float  d_gk  [KSZ];

// linspace(-1,1,96)[p] exactly as computed in fp32
__device__ __forceinline__ float nlin(int p) {
    return __fadd_rn(__fmul_rn((float)p, 2.0f/95.0f), -1.0f);
}
// Reference-exact pixel coordinate: ((fl(n - fl(v/10)) + 1)*0.5)*95
// fl(n - v/10) flush at the 0-face decides the side of the trilerp
// discontinuity at coordinate 0 — load-bearing for correctness.
__device__ __forceinline__ float defm_pix(float n, float v) {
    float t = __fadd_rn(n, -__fdiv_rn(v, 10.0f));
    t = __fadd_rn(t, 1.0f);
    t = __fmul_rn(t, 0.5f);
    return __fmul_rn(t, 95.0f);
}
__device__ __forceinline__ float grid_pix(float g) {
    float t = __fadd_rn(g, 1.0f);
    t = __fmul_rn(t, 0.5f);
    return __fmul_rn(t, 95.0f);
}

struct TrilIdx {
    int b000, b001, b010, b011, b100, b101, b110, b111;
    float fx, fy, fz;
};
__device__ __forceinline__ TrilIdx tril_idx(float X, float Y, float Z) {
    TrilIdx r;
    float xf = floorf(X), yf = floorf(Y), zf = floorf(Z);
    r.fx = X - xf; r.fy = Y - yf; r.fz = Z - zf;
    int x0 = min(max((int)xf, 0), DIMC-1); int x1 = min(x0 + 1, DIMC-1);
    int y0 = min(max((int)yf, 0), DIMC-1); int y1 = min(y0 + 1, DIMC-1);
    int z0 = min(max((int)zf, 0), DIMC-1); int z1 = min(z0 + 1, DIMC-1);
    int b00 = (z0*DIMC + y0)*DIMC, b01 = (z0*DIMC + y1)*DIMC;
    int b10 = (z1*DIMC + y0)*DIMC, b11 = (z1*DIMC + y1)*DIMC;
    r.b000 = b00+x0; r.b001 = b00+x1; r.b010 = b01+x0; r.b011 = b01+x1;
    r.b100 = b10+x0; r.b101 = b10+x1; r.b110 = b11+x0; r.b111 = b11+x1;
    return r;
}
__device__ __forceinline__ float tril_mix(float c000,float c001,float c010,float c011,
                                          float c100,float c101,float c110,float c111,
                                          float fx,float fy,float fz) {
    float lo = (c000*(1.f-fx)+c001*fx)*(1.f-fy) + (c010*(1.f-fx)+c011*fx)*fy;
    float hi = (c100*(1.f-fx)+c101*fx)*(1.f-fy) + (c110*(1.f-fx)+c111*fx)*fy;
    return lo*(1.f-fz) + hi*fz;
}
__device__ __forceinline__ float trilerp1(const float* __restrict__ p,
                                          float X, float Y, float Z) {
    TrilIdx t = tril_idx(X, Y, Z);
    return tril_mix(p[t.b000],p[t.b001],p[t.b010],p[t.b011],
                    p[t.b100],p[t.b101],p[t.b110],p[t.b111], t.fx,t.fy,t.fz);
}

// ---------------- init ----------------
__global__ void k_init(const float* __restrict__ src,
                       const float* __restrict__ seg,
                       const float* __restrict__ z0,
                       float* __restrict__ outRes0) {
    int i = blockIdx.x*blockDim.x + threadIdx.x;
    if (i < KSZ) {
        float dd = (float)(i - RAD) / 3.0f;
        float w = expf(-0.5f * dd * dd);
        float s = 0.f;
        #pragma unroll
        for (int t = 0; t < KSZ; t++) {
            float e = (float)(t - RAD) / 3.0f;
            s += expf(-0.5f * e * e);
        }
        d_gk[i] = w / s;
    }
    if (i >= NVOX) return;
    float sv = src[i];
    d_img[i] = sv;
    d_ss[i] = make_float2(sv, seg[i]);
    outRes0[i] = z0[i];
    d_rdA[i] = 0.f;
    int x = i % DIMC, y = (i/DIMC) % DIMC, z = i/(DIMC*DIMC);
    d_phi4A[i] = make_float4(nlin(x), nlin(y), nlin(z), 0.f);
}

// ---- pass 1: grad + u=-res*g + W-blur + H-blur, one z-slice per block ------
// grid (96 z, 3 c), block (32,8). dynamic smem: s_u[96][114] + s_w[114][96]
__global__ void k_blurWH(const float* __restrict__ resOld,
                         float* __restrict__ gradsOut) {
    extern __shared__ float smem[];
    float* s_u = smem;                 // [y][x+9], x in [-9,104]
    float* s_w = smem + 96*114;        // [y+9][x], y in [-9,104]
    __shared__ float s_gk[KSZ];
    int tx = threadIdx.x, ty = threadIdx.y;
    int tid = ty*32 + tx;
    int z = blockIdx.x, c = blockIdx.y;
    if (tid < KSZ) s_gk[tid] = d_gk[tid];

    // zero pad regions
    for (int idx = tid; idx < 96*18; idx += 256) {
        int row = idx / 18, p = idx % 18;
        s_u[row*114 + (p < 9 ? p : p + 96)] = 0.f;
    }
    for (int idx = tid; idx < 18*96; idx += 256) {
        int r = idx / 96, x = idx % 96;
        s_w[(r < 9 ? r : r + 96)*96 + x] = 0.f;
    }

    // grad + u into s_u
    #pragma unroll
    for (int j = 0; j < 12; j++) {
        int y = ty + 8*j;
        int ibase = (z*DIMC + y)*DIMC;
        #pragma unroll
        for (int k = 0; k < 3; k++) {
            int x = tx + 32*k;
            int i = ibase + x;
            float g;
            if (c == 0) {
                g = 0.5f*(d_img[i + (x < DIMC-1 ? 1 : 0)] - d_img[i - (x > 0 ? 1 : 0)]);
            } else if (c == 1) {
                g = 0.5f*(d_img[i + (y < DIMC-1 ? DIMC : 0)] - d_img[i - (y > 0 ? DIMC : 0)]);
            } else {
                g = 0.5f*(d_img[i + (z < DIMC-1 ? DIMC*DIMC : 0)] - d_img[i - (z > 0 ? DIMC*DIMC : 0)]);
            }
            gradsOut[(size_t)c*NVOX + i] = g;
            s_u[y*114 + x + 9] = -resOld[i] * g;
        }
    }
    __syncthreads();

    // W blur: s_u -> s_w
    #pragma unroll
    for (int j = 0; j < 12; j++) {
        int y = ty + 8*j;
        #pragma unroll
        for (int k = 0; k < 3; k++) {
            int x = tx + 32*k;
            float s = 0.f;
            #pragma unroll
            for (int t = 0; t < KSZ; t++) s += s_gk[t] * s_u[y*114 + x + t];
            s_w[(y + 9)*96 + x] = s;
        }
    }
    __syncthreads();

    // H blur: s_w -> global bufB
    #pragma unroll
    for (int j = 0; j < 12; j++) {
        int y = ty + 8*j;
        int ibase = (z*DIMC + y)*DIMC;
        #pragma unroll
        for (int k = 0; k < 3; k++) {
            int x = tx + 32*k;
            float s = 0.f;
            #pragma unroll
            for (int t = 0; t < KSZ; t++) s += s_gk[t] * s_w[(y + t)*96 + x];
            d_bufB[(size_t)c*NVOX + ibase + x] = s;
        }
    }
}

// ---- pass 2: D-blur bufB->bufA (=v) + transposed fields write --------------
// grid (3 xchunk, 96 h, 3 c), block (32,8)
__global__ void k_blurD_fields(float* __restrict__ fieldsOut) {
    __shared__ float sh[114*32];        // [z+9][tx]
    __shared__ float sh2[DIMC*33];      // [d][w] transpose staging
    __shared__ float s_gk[KSZ];
    int tx = threadIdx.x, ty = threadIdx.y;
    int tid = ty*32 + tx;
    int x0 = blockIdx.x*32, h = blockIdx.y, c = blockIdx.z;
    const float* __restrict__ in = d_bufB + (size_t)c*NVOX;
    float* __restrict__ out      = d_bufA + (size_t)c*NVOX;
    if (tid < KSZ) s_gk[tid] = d_gk[tid];
    for (int idx = tid; idx < 18*32; idx += 256) {
        int r = idx / 32, cc = idx % 32;
        sh[(r < 9 ? r : r + 96)*32 + cc] = 0.f;
    }
    #pragma unroll
    for (int k = 0; k < 12; k++) {
        int z = ty + 8*k;
        sh[(z + 9)*32 + tx] = in[(z*DIMC + h)*DIMC + x0 + tx];
    }
    __syncthreads();
    #pragma unroll
    for (int k = 0; k < 12; k++) {
        int z = ty + 8*k;
        float s = 0.f;
        #pragma unroll
        for (int t = 0; t < KSZ; t++) s += s_gk[t] * sh[(z + t)*32 + tx];
        out[(z*DIMC + h)*DIMC + x0 + tx] = s;
        sh2[z*33 + tx] = s;
    }
    __syncthreads();
    // fields[3*((w*96+h)*96+d)+c] = v_c[(d*96+h)*96+w]; coalesced in d=tx
    #pragma unroll
    for (int dk = 0; dk < 3; dk++) {
        int d = tx + 32*dk;
        #pragma unroll
        for (int wk = 0; wk < 4; wk++) {
            int w = ty + 8*wk;
            fieldsOut[3*((((size_t)(x0 + w))*DIMC + h)*DIMC + d) + c] = sh2[d*33 + w];
        }
    }
}

// ---- fused: div -> res_new ; rd warp ; phi warp ; image update --------------
// grid (3 xchunk, 12 ychunk, 96 z), block (32,8)
__global__ void k_div_warp(int par,
                           const float* __restrict__ resOld,
                           float* __restrict__ resNew,
                           const float* __restrict__ fields,
                           float* __restrict__ outImg,
                           float* __restrict__ outRd) {
    __shared__ float rs [3*10*34];
    __shared__ float v0s[3*10*34];
    __shared__ float v1s[3*10*34];
    __shared__ float v2s[3*10*34];
    int tx = threadIdx.x, ty = threadIdx.y;
    int tid = ty*32 + tx;
    int x0 = blockIdx.x*32, y0 = blockIdx.y*8, z = blockIdx.z;

    for (int li = tid; li < 3*10*34; li += 256) {
        int zp = li / 340, r2 = li % 340;
        int yy = r2 / 34, xx = r2 % 34;
        int gz = z + zp - 1, gy = y0 + yy - 1, gx = x0 + xx - 1;
        bool inb = (unsigned)gz < DIMC && (unsigned)gy < DIMC && (unsigned)gx < DIMC;
        int gi = (gz*DIMC + gy)*DIMC + gx;
        rs [li] = inb ? resOld[gi]          : 0.f;
        v0s[li] = inb ? d_bufA[gi]          : 0.f;
        v1s[li] = inb ? d_bufA[NVOX + gi]   : 0.f;
        v2s[li] = inb ? d_bufA[2*NVOX + gi] : 0.f;
    }
    __syncthreads();

    const float sw[3]  = {1.f, 2.f, 1.f};
    const float dwt[3] = {-1.f, 0.f, 1.f};
    float acc = 0.f;
    #pragma unroll
    for (int a = 0; a < 3; a++) {
        #pragma unroll
        for (int b = 0; b < 3; b++) {
            #pragma unroll
            for (int cc = 0; cc < 3; cc++) {
                int si = (a*10 + (ty + b))*34 + (tx + cc);
                float wx = sw[a]*sw[b]*dwt[cc];
                float wy = sw[a]*dwt[b]*sw[cc];
                float wz = dwt[a]*sw[b]*sw[cc];
                float r = rs[si];
                acc += (r*v0s[si])*wx + (r*v1s[si])*wy + (r*v2s[si])*wz;
            }
        }
    }
    int ci = (1*10 + (ty+1))*34 + (tx+1);
    float f = __fdiv_rn(acc * (1.0f/32.0f), 10.0f);
    float rn = rs[ci] - f;

    int x = x0 + tx, y = y0 + ty;
    int i = (z*DIMC + y)*DIMC + x;
    resNew[i] = rn;

    const float*  __restrict__ rdIn   = par ? d_rdB   : d_rdA;
    float*        __restrict__ rdOut  = par ? d_rdA   : d_rdB;
    const float4* __restrict__ phiIn  = par ? d_phi4B : d_phi4A;
    float4*       __restrict__ phiOut = par ? d_phi4A : d_phi4B;

    float nx = nlin(x), ny = nlin(y), nz = nlin(z);

    // rd warp: coords use v at transposed index = fields[3i+c]
    float Xr = defm_pix(nx, fields[3*(size_t)i+0]);
    float Yr = defm_pix(ny, fields[3*(size_t)i+1]);
    float Zr = defm_pix(nz, fields[3*(size_t)i+2]);
    float rdv = trilerp1(rdIn, Xr, Yr, Zr) + rn;
    rdOut[i] = rdv;

    // phi warp: X<-v2, Y<-v1, Z<-v0 at index i (v from shared tile center)
    float Xp = defm_pix(nx, v2s[ci]);
    float Yp = defm_pix(ny, v1s[ci]);
    float Zp = defm_pix(nz, v0s[ci]);
    TrilIdx tp = tril_idx(Xp, Yp, Zp);
    float4 q000 = phiIn[tp.b000], q001 = phiIn[tp.b001];
    float4 q010 = phiIn[tp.b010], q011 = phiIn[tp.b011];
    float4 q100 = phiIn[tp.b100], q101 = phiIn[tp.b101];
    float4 q110 = phiIn[tp.b110], q111 = phiIn[tp.b111];
    float p0 = tril_mix(q000.x,q001.x,q010.x,q011.x,q100.x,q101.x,q110.x,q111.x,tp.fx,tp.fy,tp.fz);
    float p1 = tril_mix(q000.y,q001.y,q010.y,q011.y,q100.y,q101.y,q110.y,q111.y,tp.fx,tp.fy,tp.fz);
    float p2 = tril_mix(q000.z,q001.z,q010.z,q011.z,q100.z,q101.z,q110.z,q111.z,tp.fx,tp.fy,tp.fz);
    phiOut[i] = make_float4(p0, p1, p2, 0.f);

    // image = warp(src, phi) + rd*(mu^2/L)*warp(seg, phi)
    float Xi = grid_pix(p0), Yi = grid_pix(p1), Zi = grid_pix(p2);
    TrilIdx ti = tril_idx(Xi, Yi, Zi);
    float2 s000 = d_ss[ti.b000], s001 = d_ss[ti.b001];
    float2 s010 = d_ss[ti.b010], s011 = d_ss[ti.b011];
    float2 s100 = d_ss[ti.b100], s101 = d_ss[ti.b101];
    float2 s110 = d_ss[ti.b110], s111 = d_ss[ti.b111];
    float sv = tril_mix(s000.x,s001.x,s010.x,s011.x,s100.x,s101.x,s110.x,s111.x,ti.fx,ti.fy,ti.fz);
    float mk = tril_mix(s000.y,s001.y,s010.y,s011.y,s100.y,s101.y,s110.y,s111.y,ti.fx,ti.fy,ti.fz);
    float val = sv + rdv * MU2_OVER_L * mk;
    d_img[i] = val;
    if (outImg) { outImg[i] = val; outRd[i] = rdv; }
}

extern "C" void kernel_launch(void* const* d_in, const int* in_sizes, int n_in,
                              void* d_out, int out_size) {
    (void)in_sizes; (void)n_in; (void)out_size;
    const float* src = (const float*)d_in[0];
    // d_in[1] = target (unused by reference computation)
    const float* seg = (const float*)d_in[2];
    const float* z0  = (const float*)d_in[3];

    float* out       = (float*)d_out;
    float* outImage  = out;                                   // [1,1,96,96,96]
    float* outFields = outImage + NVOX;                       // [10,1,96,96,96,3]
    float* outGrads  = outFields + (size_t)NL*3*NVOX;         // [10,1,1,3,96,96,96]
    float* outRes    = outGrads  + (size_t)NL*3*NVOX;         // [11,1,1,96,96,96]
    float* outRd     = outRes    + (size_t)(NL+1)*NVOX;       // [1,1,96,96,96]

    const int TB = 256;
    const int gN = (NVOX + TB - 1) / TB;
    const int WH_SMEM = (96*114 + 114*96) * 4;   // 87552 B

    cudaFuncSetAttribute(k_blurWH, cudaFuncAttributeMaxDynamicSharedMemorySize, WH_SMEM);

    k_init<<<gN, TB>>>(src, seg, z0, outRes);

    dim3 blk(32, 8);
    dim3 gWH(DIMC, 3);
    dim3 gD(3, DIMC, 3);
    dim3 gV(3, DIMC/8, DIMC);

    for (int it = 0; it < NL; it++) {
        int par = it & 1;
        const float* resOld = outRes + (size_t)it     * NVOX;
        float*       resNew = outRes + (size_t)(it+1) * NVOX;
        float*       fields = outFields + (size_t)it * 3 * NVOX;
        bool last = (it == NL-1);

        k_blurWH<<<gWH, blk, WH_SMEM>>>(resOld, outGrads + (size_t)it*3*NVOX);
        k_blurD_fields<<<gD, blk>>>(fields);
        k_div_warp<<<gV, blk>>>(par, resOld, resNew, fields,
                                last ? outImage : (float*)nullptr,
                                last ? outRd    : (float*)nullptr);
    }
}

// round 5
// speedup vs baseline: 1.5523x; 1.2023x over previous
#include <cuda_runtime.h>
#include <math.h>

#define DIMC 96
#define NVOX (DIMC*DIMC*DIMC)          // 884736
#define NL   10
#define RAD  9
#define KSZ  19
#define MU2_OVER_L 0.001f               // 0.1^2 / 10

// ---------------- scratch (no allocations allowed) ----------------
__device__ float  d_img [NVOX];
__device__ float  d_bufA[3*NVOX];       // v (after D blur)
__device__ float  d_bufB[3*NVOX];       // after W+H blur
__device__ float  d_rdA [NVOX];
__device__ float  d_rdB [NVOX];
__device__ float4 d_phi4A[NVOX];
__device__ float4 d_phi4B[NVOX];
__device__ float2 d_ss  [NVOX];         // (source, seg) packed
__device__ float  d_gk  [KSZ];

__device__ __forceinline__ float nlin(int p) {
    return __fadd_rn(__fmul_rn((float)p, 2.0f/95.0f), -1.0f);
}
// Reference-exact pixel coordinate: ((fl(n - fl(v/10)) + 1)*0.5)*95.
// The fl(n - v/10) flush at the 0-face decides the side of the trilerp
// discontinuity at coordinate 0 — load-bearing for correctness.
__device__ __forceinline__ float defm_pix(float n, float v) {
    float t = __fadd_rn(n, -__fdiv_rn(v, 10.0f));
    t = __fadd_rn(t, 1.0f);
    t = __fmul_rn(t, 0.5f);
    return __fmul_rn(t, 95.0f);
}
__device__ __forceinline__ float grid_pix(float g) {
    float t = __fadd_rn(g, 1.0f);
    t = __fmul_rn(t, 0.5f);
    return __fmul_rn(t, 95.0f);
}

struct TrilIdx {
    int b000, b001, b010, b011, b100, b101, b110, b111;
    float fx, fy, fz;
};
__device__ __forceinline__ TrilIdx tril_idx(float X, float Y, float Z) {
    TrilIdx r;
    float xf = floorf(X), yf = floorf(Y), zf = floorf(Z);
    r.fx = X - xf; r.fy = Y - yf; r.fz = Z - zf;
    int x0 = min(max((int)xf, 0), DIMC-1); int x1 = min(x0 + 1, DIMC-1);
    int y0 = min(max((int)yf, 0), DIMC-1); int y1 = min(y0 + 1, DIMC-1);
    int z0 = min(max((int)zf, 0), DIMC-1); int z1 = min(z0 + 1, DIMC-1);
    int b00 = (z0*DIMC + y0)*DIMC, b01 = (z0*DIMC + y1)*DIMC;
    int b10 = (z1*DIMC + y0)*DIMC, b11 = (z1*DIMC + y1)*DIMC;
    r.b000 = b00+x0; r.b001 = b00+x1; r.b010 = b01+x0; r.b011 = b01+x1;
    r.b100 = b10+x0; r.b101 = b10+x1; r.b110 = b11+x0; r.b111 = b11+x1;
    return r;
}
__device__ __forceinline__ float tril_mix(float c000,float c001,float c010,float c011,
                                          float c100,float c101,float c110,float c111,
                                          float fx,float fy,float fz) {
    float lo = (c000*(1.f-fx)+c001*fx)*(1.f-fy) + (c010*(1.f-fx)+c011*fx)*fy;
    float hi = (c100*(1.f-fx)+c101*fx)*(1.f-fy) + (c110*(1.f-fx)+c111*fx)*fy;
    return lo*(1.f-fz) + hi*fz;
}
__device__ __forceinline__ float trilerp1(const float* __restrict__ p,
                                          float X, float Y, float Z) {
    TrilIdx t = tril_idx(X, Y, Z);
    return tril_mix(p[t.b000],p[t.b001],p[t.b010],p[t.b011],
                    p[t.b100],p[t.b101],p[t.b110],p[t.b111], t.fx,t.fy,t.fz);
}

// ---------------- init ----------------
__global__ void k_init(const float* __restrict__ src,
                       const float* __restrict__ seg,
                       const float* __restrict__ z0,
                       float* __restrict__ outRes0) {
    int i = blockIdx.x*blockDim.x + threadIdx.x;
    if (i < KSZ) {
        float dd = (float)(i - RAD) / 3.0f;
        float w = expf(-0.5f * dd * dd);
        float s = 0.f;
        #pragma unroll
        for (int t = 0; t < KSZ; t++) {
            float e = (float)(t - RAD) / 3.0f;
            s += expf(-0.5f * e * e);
        }
        d_gk[i] = w / s;
    }
    if (i >= NVOX) return;
    float sv = src[i];
    d_img[i] = sv;
    d_ss[i] = make_float2(sv, seg[i]);
    outRes0[i] = z0[i];
    d_rdA[i] = 0.f;
    int x = i % DIMC, y = (i/DIMC) % DIMC, z = i/(DIMC*DIMC);
    d_phi4A[i] = make_float4(nlin(x), nlin(y), nlin(z), 0.f);
}

// ---- pass 1: grad + u=-res*g + W-blur + H-blur, one z-slice per block ------
// grid (96 z, 3 c), block (32,8). smem: s_u[96][115] (x-halo) + s_w[114][97] (y-halo)
#define SU_STR 115
#define SW_STR 97
__global__ void __launch_bounds__(256) k_blurWH(const float* __restrict__ resOld,
                                                float* __restrict__ gradsOut) {
    extern __shared__ float smem[];
    float* s_u = smem;                 // [y][x+9], x in [-9,104], stride 115
    float* s_w = smem + 96*SU_STR;     // [y+9][x], y in [-9,104], stride 97
    __shared__ float s_gk[KSZ];
    int tx = threadIdx.x, ty = threadIdx.y;
    int tid = ty*32 + tx;
    int z = blockIdx.x, c = blockIdx.y;
    if (tid < KSZ) s_gk[tid] = d_gk[tid];

    // zero halos
    for (int idx = tid; idx < 96*18; idx += 256) {
        int row = idx / 18, p = idx % 18;
        s_u[row*SU_STR + (p < 9 ? p : p + 96)] = 0.f;
    }
    for (int idx = tid; idx < 18*96; idx += 256) {
        int r = idx / 96, x = idx % 96;
        s_w[(r < 9 ? r : r + 96)*SW_STR + x] = 0.f;
    }

    // stage 1: grad + u into s_u
    #pragma unroll
    for (int j = 0; j < 12; j++) {
        int y = ty + 8*j;
        int ibase = (z*DIMC + y)*DIMC;
        #pragma unroll
        for (int k = 0; k < 3; k++) {
            int x = tx + 32*k;
            int i = ibase + x;
            float g;
            if (c == 0) {
                g = 0.5f*(d_img[i + (x < DIMC-1 ? 1 : 0)] - d_img[i - (x > 0 ? 1 : 0)]);
            } else if (c == 1) {
                g = 0.5f*(d_img[i + (y < DIMC-1 ? DIMC : 0)] - d_img[i - (y > 0 ? DIMC : 0)]);
            } else {
                g = 0.5f*(d_img[i + (z < DIMC-1 ? DIMC*DIMC : 0)] - d_img[i - (z > 0 ? DIMC*DIMC : 0)]);
            }
            gradsOut[(size_t)c*NVOX + i] = g;
            s_u[y*SU_STR + x + 9] = -resOld[i] * g;
        }
    }
    __syncthreads();

    // stage 2: W blur via register window. 768 segments = (xs 0..7)*96 + y
    for (int segIdx = tid; segIdx < 768; segIdx += 256) {
        int y  = segIdx % 96;
        int xs = (segIdx / 96) * 12;
        float r[30];
        #pragma unroll
        for (int k = 0; k < 30; k++) r[k] = s_u[y*SU_STR + xs + k];
        #pragma unroll
        for (int j = 0; j < 12; j++) {
            float s = 0.f;
            #pragma unroll
            for (int t = 0; t < KSZ; t++) s += s_gk[t] * r[j + t];
            s_w[(y + 9)*SW_STR + xs + j] = s;
        }
    }
    __syncthreads();

    // stage 3: H blur via register window. segments = (ys 0..7)*96 + x
    for (int segIdx = tid; segIdx < 768; segIdx += 256) {
        int x  = segIdx % 96;
        int ys = (segIdx / 96) * 12;
        float r[30];
        #pragma unroll
        for (int k = 0; k < 30; k++) r[k] = s_w[(ys + k)*SW_STR + x];
        #pragma unroll
        for (int j = 0; j < 12; j++) {
            float s = 0.f;
            #pragma unroll
            for (int t = 0; t < KSZ; t++) s += s_gk[t] * r[j + t];
            d_bufB[(size_t)c*NVOX + (z*DIMC + ys + j)*DIMC + x] = s;
        }
    }
}

// ---- pass 2: D-blur bufB->bufA (=v) + transposed fields write --------------
// grid (3 xchunk, 96 h, 3 c), block (32,8): ty = z-segment (12 z each)
__global__ void __launch_bounds__(256) k_blurD_fields(float* __restrict__ fieldsOut) {
    __shared__ float sh2[DIMC*33];      // [z][w] transpose staging
    __shared__ float s_gk[KSZ];
    int tx = threadIdx.x, ty = threadIdx.y;
    int tid = ty*32 + tx;
    int x0 = blockIdx.x*32, h = blockIdx.y, c = blockIdx.z;
    const float* __restrict__ in = d_bufB + (size_t)c*NVOX;
    float* __restrict__ out      = d_bufA + (size_t)c*NVOX;
    if (tid < KSZ) s_gk[tid] = d_gk[tid];
    __syncthreads();

    int x = x0 + tx;
    int zs = ty * 12;
    float r[30];
    #pragma unroll
    for (int k = 0; k < 30; k++) {
        int z = zs + k - 9;
        r[k] = ((unsigned)z < (unsigned)DIMC) ? in[(z*DIMC + h)*DIMC + x] : 0.f;
    }
    #pragma unroll
    for (int j = 0; j < 12; j++) {
        float s = 0.f;
        #pragma unroll
        for (int t = 0; t < KSZ; t++) s += s_gk[t] * r[j + t];
        int z = zs + j;
        out[(z*DIMC + h)*DIMC + x] = s;
        sh2[z*33 + tx] = s;
    }
    __syncthreads();
    // fields[3*((w*96+h)*96+d)+c] = v_c[(d*96+h)*96+w]; coalesced in d=tx
    #pragma unroll
    for (int dk = 0; dk < 3; dk++) {
        int d = tx + 32*dk;
        #pragma unroll
        for (int wk = 0; wk < 4; wk++) {
            int w = ty + 8*wk;
            fieldsOut[3*((((size_t)(x0 + w))*DIMC + h)*DIMC + d) + c] = sh2[d*33 + w];
        }
    }
}

// ---- fused: separable div -> res_new ; rd warp ; phi warp ; image ----------
// grid (3 xchunk, 12 ychunk, 96 z), block (32,8)
__global__ void __launch_bounds__(256) k_div_warp(int par,
                           const float* __restrict__ resOld,
                           float* __restrict__ resNew,
                           const float* __restrict__ fields,
                           float* __restrict__ outImg,
                           float* __restrict__ outRd) {
    __shared__ float p0[3*10*34], p1[3*10*34], p2[3*10*34];   // r*v tiles
    __shared__ float q0[10*34], q1[10*34], q2[10*34];          // z-collapsed
    __shared__ float r0[8*34], r12[8*34];                      // y-collapsed
    int tx = threadIdx.x, ty = threadIdx.y;
    int tid = ty*32 + tx;
    int x0 = blockIdx.x*32, y0 = blockIdx.y*8, z = blockIdx.z;

    for (int li = tid; li < 3*10*34; li += 256) {
        int zp = li / 340, r2 = li % 340;
        int yy = r2 / 34, xx = r2 % 34;
        int gz = z + zp - 1, gy = y0 + yy - 1, gx = x0 + xx - 1;
        bool inb = (unsigned)gz < DIMC && (unsigned)gy < DIMC && (unsigned)gx < DIMC;
        int gi = (gz*DIMC + gy)*DIMC + gx;
        float rr = inb ? resOld[gi] : 0.f;
        p0[li] = inb ? rr*d_bufA[gi]          : 0.f;
        p1[li] = inb ? rr*d_bufA[NVOX + gi]   : 0.f;
        p2[li] = inb ? rr*d_bufA[2*NVOX + gi] : 0.f;
    }
    __syncthreads();

    // z-collapse: q0=S_z p0, q1=S_z p1, q2=D_z p2
    for (int li = tid; li < 340; li += 256) {
        q0[li] = p0[li] + 2.f*p0[340+li] + p0[680+li];
        q1[li] = p1[li] + 2.f*p1[340+li] + p1[680+li];
        q2[li] = p2[680+li] - p2[li];
    }
    __syncthreads();

    // y-collapse: r0=S_y q0 ; r12 = D_y q1 + S_y q2
    for (int li = tid; li < 272; li += 256) {
        int base = li;   // yo*34 + x, yo = li/34
        r0[li]  = q0[base] + 2.f*q0[base+34] + q0[base+68];
        float t1 = q1[base+68] - q1[base];
        float t2 = q2[base] + 2.f*q2[base+34] + q2[base+68];
        r12[li] = t1 + t2;
    }
    __syncthreads();

    // x-collapse + res update
    int li = ty*34 + tx;
    float acc = (r0[li+2] - r0[li]) + (r12[li] + 2.f*r12[li+1] + r12[li+2]);
    float f = __fdiv_rn(acc * (1.0f/32.0f), 10.0f);

    int x = x0 + tx, y = y0 + ty;
    int i = (z*DIMC + y)*DIMC + x;
    float rn = resOld[i] - f;
    resNew[i] = rn;

    const float*  __restrict__ rdIn   = par ? d_rdB   : d_rdA;
    float*        __restrict__ rdOut  = par ? d_rdA   : d_rdB;
    const float4* __restrict__ phiIn  = par ? d_phi4B : d_phi4A;
    float4*       __restrict__ phiOut = par ? d_phi4A : d_phi4B;

    float nx = nlin(x), ny = nlin(y), nz = nlin(z);

    // rd warp: coords use v at transposed index = fields[3i+c]
    float Xr = defm_pix(nx, fields[3*(size_t)i+0]);
    float Yr = defm_pix(ny, fields[3*(size_t)i+1]);
    float Zr = defm_pix(nz, fields[3*(size_t)i+2]);
    float rdv = trilerp1(rdIn, Xr, Yr, Zr) + rn;
    rdOut[i] = rdv;

    // phi warp: X<-v2, Y<-v1, Z<-v0 at index i
    float Xp = defm_pix(nx, d_bufA[2*NVOX+i]);
    float Yp = defm_pix(ny, d_bufA[NVOX+i]);
    float Zp = defm_pix(nz, d_bufA[i]);
    TrilIdx tp = tril_idx(Xp, Yp, Zp);
    float4 q000 = phiIn[tp.b000], q001 = phiIn[tp.b001];
    float4 q010 = phiIn[tp.b010], q011 = phiIn[tp.b011];
    float4 q100 = phiIn[tp.b100], q101 = phiIn[tp.b101];
    float4 q110 = phiIn[tp.b110], q111 = phiIn[tp.b111];
    float g0 = tril_mix(q000.x,q001.x,q010.x,q011.x,q100.x,q101.x,q110.x,q111.x,tp.fx,tp.fy,tp.fz);
    float g1 = tril_mix(q000.y,q001.y,q010.y,q011.y,q100.y,q101.y,q110.y,q111.y,tp.fx,tp.fy,tp.fz);
    float g2 = tril_mix(q000.z,q001.z,q010.z,q011.z,q100.z,q101.z,q110.z,q111.z,tp.fx,tp.fy,tp.fz);
    phiOut[i] = make_float4(g0, g1, g2, 0.f);

    // image = warp(src, phi) + rd*(mu^2/L)*warp(seg, phi)
    float Xi = grid_pix(g0), Yi = grid_pix(g1), Zi = grid_pix(g2);
    TrilIdx ti = tril_idx(Xi, Yi, Zi);
    float2 s000 = d_ss[ti.b000], s001 = d_ss[ti.b001];
    float2 s010 = d_ss[ti.b010], s011 = d_ss[ti.b011];
    float2 s100 = d_ss[ti.b100], s101 = d_ss[ti.b101];
    float2 s110 = d_ss[ti.b110], s111 = d_ss[ti.b111];
    float sv = tril_mix(s000.x,s001.x,s010.x,s011.x,s100.x,s101.x,s110.x,s111.x,ti.fx,ti.fy,ti.fz);
    float mk = tril_mix(s000.y,s001.y,s010.y,s011.y,s100.y,s101.y,s110.y,s111.y,ti.fx,ti.fy,ti.fz);
    float val = sv + rdv * MU2_OVER_L * mk;
    d_img[i] = val;
    if (outImg) { outImg[i] = val; outRd[i] = rdv; }
}

extern "C" void kernel_launch(void* const* d_in, const int* in_sizes, int n_in,
                              void* d_out, int out_size) {
    (void)in_sizes; (void)n_in; (void)out_size;
    const float* src = (const float*)d_in[0];
    // d_in[1] = target (unused by reference computation)
    const float* seg = (const float*)d_in[2];
    const float* z0  = (const float*)d_in[3];

    float* out       = (float*)d_out;
    float* outImage  = out;                                   // [1,1,96,96,96]
    float* outFields = outImage + NVOX;                       // [10,1,96,96,96,3]
    float* outGrads  = outFields + (size_t)NL*3*NVOX;         // [10,1,1,3,96,96,96]
    float* outRes    = outGrads  + (size_t)NL*3*NVOX;         // [11,1,1,96,96,96]
    float* outRd     = outRes    + (size_t)(NL+1)*NVOX;       // [1,1,96,96,96]

    const int TB = 256;
    const int gN = (NVOX + TB - 1) / TB;
    const int WH_SMEM = (96*SU_STR + 114*SW_STR) * 4;   // 88392 B

    cudaFuncSetAttribute(k_blurWH, cudaFuncAttributeMaxDynamicSharedMemorySize, WH_SMEM);

    k_init<<<gN, TB>>>(src, seg, z0, outRes);

    dim3 blk(32, 8);
    dim3 gWH(DIMC, 3);
    dim3 gD(3, DIMC, 3);
    dim3 gV(3, DIMC/8, DIMC);

    for (int it = 0; it < NL; it++) {
        int par = it & 1;
        const float* resOld = outRes + (size_t)it     * NVOX;
        float*       resNew = outRes + (size_t)(it+1) * NVOX;
        float*       fields = outFields + (size_t)it * 3 * NVOX;
        bool last = (it == NL-1);

        k_blurWH<<<gWH, blk, WH_SMEM>>>(resOld, outGrads + (size_t)it*3*NVOX);
        k_blurD_fields<<<gD, blk>>>(fields);
        k_div_warp<<<gV, blk>>>(par, resOld, resNew, fields,
                                last ? outImage : (float*)nullptr,
                                last ? outRd    : (float*)nullptr);
    }
}

// round 6
// speedup vs baseline: 1.5528x; 1.0003x over previous
#include <cuda_runtime.h>
#include <math.h>

#define DIMC 96
#define NVOX (DIMC*DIMC*DIMC)          // 884736
#define NL   10
#define RAD  9
#define KSZ  19
#define MU2_OVER_L 0.001f               // 0.1^2 / 10

// ---------------- scratch (no allocations allowed) ----------------
__device__ float  d_img [NVOX];
__device__ float  d_bufA[3*NVOX];       // v (after D blur)
__device__ float  d_bufB[3*NVOX];       // after W+H blur
__device__ float  d_rdA [NVOX];
__device__ float  d_rdB [NVOX];
__device__ float4 d_phi4A[NVOX];
__device__ float4 d_phi4B[NVOX];
__device__ float2 d_ss  [NVOX];         // (source, seg) packed
__device__ float  d_gk  [KSZ];

__device__ __forceinline__ float nlin(int p) {
    return __fadd_rn(__fmul_rn((float)p, 2.0f/95.0f), -1.0f);
}
// Reference-exact pixel coordinate: ((fl(n - fl(v/10)) + 1)*0.5)*95.
// The fl(n - v/10) flush at the 0-face decides the side of the trilerp
// discontinuity at coordinate 0 — load-bearing for correctness.
__device__ __forceinline__ float defm_pix(float n, float v) {
    float t = __fadd_rn(n, -__fdiv_rn(v, 10.0f));
    t = __fadd_rn(t, 1.0f);
    t = __fmul_rn(t, 0.5f);
    return __fmul_rn(t, 95.0f);
}
__device__ __forceinline__ float grid_pix(float g) {
    float t = __fadd_rn(g, 1.0f);
    t = __fmul_rn(t, 0.5f);
    return __fmul_rn(t, 95.0f);
}

struct TrilIdx {
    int b000, b001, b010, b011, b100, b101, b110, b111;
    float fx, fy, fz;
};
__device__ __forceinline__ TrilIdx tril_idx(float X, float Y, float Z) {
    TrilIdx r;
    float xf = floorf(X), yf = floorf(Y), zf = floorf(Z);
    r.fx = X - xf; r.fy = Y - yf; r.fz = Z - zf;
    int x0 = min(max((int)xf, 0), DIMC-1); int x1 = min(x0 + 1, DIMC-1);
    int y0 = min(max((int)yf, 0), DIMC-1); int y1 = min(y0 + 1, DIMC-1);
    int z0 = min(max((int)zf, 0), DIMC-1); int z1 = min(z0 + 1, DIMC-1);
    int b00 = (z0*DIMC + y0)*DIMC, b01 = (z0*DIMC + y1)*DIMC;
    int b10 = (z1*DIMC + y0)*DIMC, b11 = (z1*DIMC + y1)*DIMC;
    r.b000 = b00+x0; r.b001 = b00+x1; r.b010 = b01+x0; r.b011 = b01+x1;
    r.b100 = b10+x0; r.b101 = b10+x1; r.b110 = b11+x0; r.b111 = b11+x1;
    return r;
}
__device__ __forceinline__ float tril_mix(float c000,float c001,float c010,float c011,
                                          float c100,float c101,float c110,float c111,
                                          float fx,float fy,float fz) {
    float lo = (c000*(1.f-fx)+c001*fx)*(1.f-fy) + (c010*(1.f-fx)+c011*fx)*fy;
    float hi = (c100*(1.f-fx)+c101*fx)*(1.f-fy) + (c110*(1.f-fx)+c111*fx)*fy;
    return lo*(1.f-fz) + hi*fz;
}
__device__ __forceinline__ float trilerp1(const float* __restrict__ p,
                                          float X, float Y, float Z) {
    TrilIdx t = tril_idx(X, Y, Z);
    return tril_mix(p[t.b000],p[t.b001],p[t.b010],p[t.b011],
                    p[t.b100],p[t.b101],p[t.b110],p[t.b111], t.fx,t.fy,t.fz);
}

// ---------------- init ----------------
__global__ void k_init(const float* __restrict__ src,
                       const float* __restrict__ seg,
                       const float* __restrict__ z0,
                       float* __restrict__ outRes0) {
    int i = blockIdx.x*blockDim.x + threadIdx.x;
    if (i < KSZ) {
        float dd = (float)(i - RAD) / 3.0f;
        float w = expf(-0.5f * dd * dd);
        float s = 0.f;
        #pragma unroll
        for (int t = 0; t < KSZ; t++) {
            float e = (float)(t - RAD) / 3.0f;
            s += expf(-0.5f * e * e);
        }
        d_gk[i] = w / s;
    }
    if (i >= NVOX) return;
    float sv = src[i];
    d_img[i] = sv;
    d_ss[i] = make_float2(sv, seg[i]);
    outRes0[i] = z0[i];
    d_rdA[i] = 0.f;
    int x = i % DIMC, y = (i/DIMC) % DIMC, z = i/(DIMC*DIMC);
    d_phi4A[i] = make_float4(nlin(x), nlin(y), nlin(z), 0.f);
}

// ---- pass 1: grad + u=-res*g + W-blur + H-blur, one z-slice per block ------
// grid (96 z, 3 c), block (32,8). smem: s_u[96][115] (x-halo) + s_w[114][97] (y-halo)
#define SU_STR 115
#define SW_STR 97
__global__ void __launch_bounds__(256) k_blurWH(const float* __restrict__ resOld,
                                                float* __restrict__ gradsOut) {
    extern __shared__ float smem[];
    float* s_u = smem;                 // [y][x+9], x in [-9,104], stride 115
    float* s_w = smem + 96*SU_STR;     // [y+9][x], y in [-9,104], stride 97
    __shared__ float s_gk[KSZ];
    int tx = threadIdx.x, ty = threadIdx.y;
    int tid = ty*32 + tx;
    int z = blockIdx.x, c = blockIdx.y;
    if (tid < KSZ) s_gk[tid] = d_gk[tid];

    // zero halos
    for (int idx = tid; idx < 96*18; idx += 256) {
        int row = idx / 18, p = idx % 18;
        s_u[row*SU_STR + (p < 9 ? p : p + 96)] = 0.f;
    }
    for (int idx = tid; idx < 18*96; idx += 256) {
        int r = idx / 96, x = idx % 96;
        s_w[(r < 9 ? r : r + 96)*SW_STR + x] = 0.f;
    }

    // stage 1: grad + u into s_u
    #pragma unroll
    for (int j = 0; j < 12; j++) {
        int y = ty + 8*j;
        int ibase = (z*DIMC + y)*DIMC;
        #pragma unroll
        for (int k = 0; k < 3; k++) {
            int x = tx + 32*k;
            int i = ibase + x;
            float g;
            if (c == 0) {
                g = 0.5f*(d_img[i + (x < DIMC-1 ? 1 : 0)] - d_img[i - (x > 0 ? 1 : 0)]);
            } else if (c == 1) {
                g = 0.5f*(d_img[i + (y < DIMC-1 ? DIMC : 0)] - d_img[i - (y > 0 ? DIMC : 0)]);
            } else {
                g = 0.5f*(d_img[i + (z < DIMC-1 ? DIMC*DIMC : 0)] - d_img[i - (z > 0 ? DIMC*DIMC : 0)]);
            }
            gradsOut[(size_t)c*NVOX + i] = g;
            s_u[y*SU_STR + x + 9] = -resOld[i] * g;
        }
    }
    __syncthreads();

    // stage 2: W blur via register window. 768 segments = (xs 0..7)*96 + y
    for (int segIdx = tid; segIdx < 768; segIdx += 256) {
        int y  = segIdx % 96;
        int xs = (segIdx / 96) * 12;
        float r[30];
        #pragma unroll
        for (int k = 0; k < 30; k++) r[k] = s_u[y*SU_STR + xs + k];
        #pragma unroll
        for (int j = 0; j < 12; j++) {
            float s = 0.f;
            #pragma unroll
            for (int t = 0; t < KSZ; t++) s += s_gk[t] * r[j + t];
            s_w[(y + 9)*SW_STR + xs + j] = s;
        }
    }
    __syncthreads();

    // stage 3: H blur via register window. segments = (ys 0..7)*96 + x
    for (int segIdx = tid; segIdx < 768; segIdx += 256) {
        int x  = segIdx % 96;
        int ys = (segIdx / 96) * 12;
        float r[30];
        #pragma unroll
        for (int k = 0; k < 30; k++) r[k] = s_w[(ys + k)*SW_STR + x];
        #pragma unroll
        for (int j = 0; j < 12; j++) {
            float s = 0.f;
            #pragma unroll
            for (int t = 0; t < KSZ; t++) s += s_gk[t] * r[j + t];
            d_bufB[(size_t)c*NVOX + (z*DIMC + ys + j)*DIMC + x] = s;
        }
    }
}

// ---- pass 2: D-blur bufB->bufA (=v) + transposed fields write --------------
// grid (3 xchunk, 96 h, 3 c), block (32,8): ty = z-segment (12 z each)
__global__ void __launch_bounds__(256) k_blurD_fields(float* __restrict__ fieldsOut) {
    __shared__ float sh2[DIMC*33];      // [z][w] transpose staging
    __shared__ float s_gk[KSZ];
    int tx = threadIdx.x, ty = threadIdx.y;
    int tid = ty*32 + tx;
    int x0 = blockIdx.x*32, h = blockIdx.y, c = blockIdx.z;
    const float* __restrict__ in = d_bufB + (size_t)c*NVOX;
    float* __restrict__ out      = d_bufA + (size_t)c*NVOX;
    if (tid < KSZ) s_gk[tid] = d_gk[tid];
    __syncthreads();

    int x = x0 + tx;
    int zs = ty * 12;
    float r[30];
    #pragma unroll
    for (int k = 0; k < 30; k++) {
        int z = zs + k - 9;
        r[k] = ((unsigned)z < (unsigned)DIMC) ? in[(z*DIMC + h)*DIMC + x] : 0.f;
    }
    #pragma unroll
    for (int j = 0; j < 12; j++) {
        float s = 0.f;
        #pragma unroll
        for (int t = 0; t < KSZ; t++) s += s_gk[t] * r[j + t];
        int z = zs + j;
        out[(z*DIMC + h)*DIMC + x] = s;
        sh2[z*33 + tx] = s;
    }
    __syncthreads();
    // fields[3*((w*96+h)*96+d)+c] = v_c[(d*96+h)*96+w]; coalesced in d=tx
    #pragma unroll
    for (int dk = 0; dk < 3; dk++) {
        int d = tx + 32*dk;
        #pragma unroll
        for (int wk = 0; wk < 4; wk++) {
            int w = ty + 8*wk;
            fieldsOut[3*((((size_t)(x0 + w))*DIMC + h)*DIMC + d) + c] = sh2[d*33 + w];
        }
    }
}

// ---- fused: separable div -> res_new ; rd warp ; phi warp ; image ----------
// grid (3 xchunk, 6 ychunk, 96 z), block (32,16)
__global__ void __launch_bounds__(512) k_div_warp(int par,
                           const float* __restrict__ resOld,
                           float* __restrict__ resNew,
                           const float* __restrict__ fields,
                           float* __restrict__ outImg,
                           float* __restrict__ outRd) {
    __shared__ float q0[18*34], q1[18*34], q2[18*34];   // z-collapsed r*v
    __shared__ float r0[16*34], r12[16*34];             // y-collapsed
    int tx = threadIdx.x, ty = threadIdx.y;
    int tid = ty*32 + tx;
    int x0 = blockIdx.x*32, y0 = blockIdx.y*16, z = blockIdx.z;

    // load + fused z-collapse: q0=S_z(r*v0), q1=S_z(r*v1), q2=D_z(r*v2)
    int zm = z - 1, zpp = z + 1;
    bool zmv = (zm >= 0), zpv = (zpp < DIMC);
    for (int li = tid; li < 18*34; li += 512) {
        int yy = li / 34, xx = li - yy*34;
        int gy = y0 + yy - 1, gx = x0 + xx - 1;
        bool xyv = (unsigned)gy < DIMC && (unsigned)gx < DIMC;
        int gi0 = (gy*DIMC + gx);
        float a0, a1, a2, b2;
        // center plane (weight 2 / D_z weight 0)
        {
            int gi = z*DIMC*DIMC + gi0;
            float rr = xyv ? resOld[gi] : 0.f;
            a0 = 2.f*(rr * (xyv ? d_bufA[gi] : 0.f));
            a1 = 2.f*(rr * (xyv ? d_bufA[NVOX+gi] : 0.f));
            a2 = 0.f; b2 = 0.f;
        }
        if (xyv & zmv) {
            int gi = zm*DIMC*DIMC + gi0;
            float rr = resOld[gi];
            a0 = (rr*d_bufA[gi]) + a0;              // p0(z-1) + 2*p0(z)
            a1 = (rr*d_bufA[NVOX+gi]) + a1;
            a2 = rr*d_bufA[2*NVOX+gi];              // p2(z-1)
        }
        if (xyv & zpv) {
            int gi = zpp*DIMC*DIMC + gi0;
            float rr = resOld[gi];
            a0 = a0 + rr*d_bufA[gi];                // (+ p0(z+1))
            a1 = a1 + rr*d_bufA[NVOX+gi];
            b2 = rr*d_bufA[2*NVOX+gi];              // p2(z+1)
        }
        q0[li] = a0;
        q1[li] = a1;
        q2[li] = b2 - a2;
    }
    __syncthreads();

    // y-collapse: r0 = S_y q0 ; r12 = D_y q1 + S_y q2
    for (int li = tid; li < 16*34; li += 512) {
        r0[li]  = q0[li] + 2.f*q0[li+34] + q0[li+68];
        float t1 = q1[li+68] - q1[li];
        float t2 = q2[li] + 2.f*q2[li+34] + q2[li+68];
        r12[li] = t1 + t2;
    }
    __syncthreads();

    // x-collapse + res update
    int li = ty*34 + tx;
    float acc = (r0[li+2] - r0[li]) + (r12[li] + 2.f*r12[li+1] + r12[li+2]);
    float f = __fdiv_rn(acc * (1.0f/32.0f), 10.0f);

    int x = x0 + tx, y = y0 + ty;
    int i = (z*DIMC + y)*DIMC + x;
    float rn = resOld[i] - f;
    resNew[i] = rn;

    const float*  __restrict__ rdIn   = par ? d_rdB   : d_rdA;
    float*        __restrict__ rdOut  = par ? d_rdA   : d_rdB;
    const float4* __restrict__ phiIn  = par ? d_phi4B : d_phi4A;
    float4*       __restrict__ phiOut = par ? d_phi4A : d_phi4B;

    float nx = nlin(x), ny = nlin(y), nz = nlin(z);

    // rd warp: coords use v at transposed index = fields[3i+c]
    float Xr = defm_pix(nx, fields[3*(size_t)i+0]);
    float Yr = defm_pix(ny, fields[3*(size_t)i+1]);
    float Zr = defm_pix(nz, fields[3*(size_t)i+2]);
    float rdv = trilerp1(rdIn, Xr, Yr, Zr) + rn;
    rdOut[i] = rdv;

    // phi warp: X<-v2, Y<-v1, Z<-v0 at index i
    float Xp = defm_pix(nx, d_bufA[2*NVOX+i]);
    float Yp = defm_pix(ny, d_bufA[NVOX+i]);
    float Zp = defm_pix(nz, d_bufA[i]);
    TrilIdx tp = tril_idx(Xp, Yp, Zp);
    float4 q000 = phiIn[tp.b000], q001 = phiIn[tp.b001];
    float4 q010 = phiIn[tp.b010], q011 = phiIn[tp.b011];
    float4 q100 = phiIn[tp.b100], q101 = phiIn[tp.b101];
    float4 q110 = phiIn[tp.b110], q111 = phiIn[tp.b111];
    float g0 = tril_mix(q000.x,q001.x,q010.x,q011.x,q100.x,q101.x,q110.x,q111.x,tp.fx,tp.fy,tp.fz);
    float g1 = tril_mix(q000.y,q001.y,q010.y,q011.y,q100.y,q101.y,q110.y,q111.y,tp.fx,tp.fy,tp.fz);
    float g2 = tril_mix(q000.z,q001.z,q010.z,q011.z,q100.z,q101.z,q110.z,q111.z,tp.fx,tp.fy,tp.fz);
    phiOut[i] = make_float4(g0, g1, g2, 0.f);

    // image = warp(src, phi) + rd*(mu^2/L)*warp(seg, phi)
    float Xi = grid_pix(g0), Yi = grid_pix(g1), Zi = grid_pix(g2);
    TrilIdx ti = tril_idx(Xi, Yi, Zi);
    float2 s000 = d_ss[ti.b000], s001 = d_ss[ti.b001];
    float2 s010 = d_ss[ti.b010], s011 = d_ss[ti.b011];
    float2 s100 = d_ss[ti.b100], s101 = d_ss[ti.b101];
    float2 s110 = d_ss[ti.b110], s111 = d_ss[ti.b111];
    float sv = tril_mix(s000.x,s001.x,s010.x,s011.x,s100.x,s101.x,s110.x,s111.x,ti.fx,ti.fy,ti.fz);
    float mk = tril_mix(s000.y,s001.y,s010.y,s011.y,s100.y,s101.y,s110.y,s111.y,ti.fx,ti.fy,ti.fz);
    float val = sv + rdv * MU2_OVER_L * mk;
    d_img[i] = val;
    if (outImg) { outImg[i] = val; outRd[i] = rdv; }
}

extern "C" void kernel_launch(void* const* d_in, const int* in_sizes, int n_in,
                              void* d_out, int out_size) {
    (void)in_sizes; (void)n_in; (void)out_size;
    const float* src = (const float*)d_in[0];
    // d_in[1] = target (unused by reference computation)
    const float* seg = (const float*)d_in[2];
    const float* z0  = (const float*)d_in[3];

    float* out       = (float*)d_out;
    float* outImage  = out;                                   // [1,1,96,96,96]
    float* outFields = outImage + NVOX;                       // [10,1,96,96,96,3]
    float* outGrads  = outFields + (size_t)NL*3*NVOX;         // [10,1,1,3,96,96,96]
    float* outRes    = outGrads  + (size_t)NL*3*NVOX;         // [11,1,1,96,96,96]
    float* outRd     = outRes    + (size_t)(NL+1)*NVOX;       // [1,1,96,96,96]

    const int TB = 256;
    const int gN = (NVOX + TB - 1) / TB;
    const int WH_SMEM = (96*SU_STR + 114*SW_STR) * 4;   // 88392 B

    cudaFuncSetAttribute(k_blurWH, cudaFuncAttributeMaxDynamicSharedMemorySize, WH_SMEM);

    k_init<<<gN, TB>>>(src, seg, z0, outRes);

    dim3 blk(32, 8);
    dim3 blkV(32, 16);
    dim3 gWH(DIMC, 3);
    dim3 gD(3, DIMC, 3);
    dim3 gV(3, DIMC/16, DIMC);

    for (int it = 0; it < NL; it++) {
        int par = it & 1;
        const float* resOld = outRes + (size_t)it     * NVOX;
        float*       resNew = outRes + (size_t)(it+1) * NVOX;
        float*       fields = outFields + (size_t)it * 3 * NVOX;
        bool last = (it == NL-1);

        k_blurWH<<<gWH, blk, WH_SMEM>>>(resOld, outGrads + (size_t)it*3*NVOX);
        k_blurD_fields<<<gD, blk>>>(fields);
        k_div_warp<<<gV, blkV>>>(par, resOld, resNew, fields,
                                 last ? outImage : (float*)nullptr,
                                 last ? outRd    : (float*)nullptr);
    }
}